// round 4
// baseline (speedup 1.0000x reference)
#include <cuda_runtime.h>

// Problem constants
#define Dm 1024
#define Hn 16
#define HD 64
#define Bb 8
#define Ss 1024
#define M_ROWS (Bb * Ss)          // 8192

// Scratch (no runtime allocation allowed)
__device__ float g_q[(size_t)M_ROWS * Dm];        // 33.5 MB
__device__ float g_kv[(size_t)M_ROWS * 2 * Dm];   // 67 MB
__device__ float g_heads[(size_t)M_ROWS * Dm];    // 33.5 MB

// ---------------------------------------------------------------------------
// Generic fp32 GEMM + bias: C[M,N] = A[M,K] @ W[K,N] + bias[N]
// Tile 128x128x16, 256 threads, 8x8 microtile. All dims divisible (M=8192,
// N in {1024,2048}, K=1024), so no bounds checks.
// ---------------------------------------------------------------------------
__global__ __launch_bounds__(256, 2)
void gemm_bias_kernel(const float* __restrict__ A, const float* __restrict__ W,
                      const float* __restrict__ bias, float* __restrict__ C,
                      int M, int N, int K)
{
    __shared__ float As[16][132];   // A tile transposed [k][m], padded (132%8==4 -> 2-ish way store)
    __shared__ float Bs[16][128];   // B tile [k][n]

    const int bm  = blockIdx.y * 128;
    const int bn  = blockIdx.x * 128;
    const int tid = threadIdx.x;
    const int tx  = tid & 15;       // micro col group
    const int ty  = tid >> 4;       // micro row group

    // Loader mapping
    const int aRow = tid >> 2;            // 0..63 (plus +64 for 2nd vec)
    const int aC4  = (tid & 3) * 4;       // 0,4,8,12
    const int bRow = tid >> 5;            // 0..7  (plus +8)
    const int bC4  = (tid & 31) * 4;      // 0..124

    float acc[8][8];
    #pragma unroll
    for (int i = 0; i < 8; i++)
        #pragma unroll
        for (int j = 0; j < 8; j++) acc[i][j] = 0.f;

    for (int k0 = 0; k0 < K; k0 += 16) {
        const float4 a0 = *(const float4*)(A + (size_t)(bm + aRow)      * K + k0 + aC4);
        const float4 a1 = *(const float4*)(A + (size_t)(bm + aRow + 64) * K + k0 + aC4);
        const float4 b0 = *(const float4*)(W + (size_t)(k0 + bRow)     * N + bn + bC4);
        const float4 b1 = *(const float4*)(W + (size_t)(k0 + bRow + 8) * N + bn + bC4);

        __syncthreads();   // previous tile's compute done before overwrite
        As[aC4 + 0][aRow] = a0.x; As[aC4 + 1][aRow] = a0.y;
        As[aC4 + 2][aRow] = a0.z; As[aC4 + 3][aRow] = a0.w;
        As[aC4 + 0][aRow + 64] = a1.x; As[aC4 + 1][aRow + 64] = a1.y;
        As[aC4 + 2][aRow + 64] = a1.z; As[aC4 + 3][aRow + 64] = a1.w;
        *(float4*)&Bs[bRow][bC4]     = b0;
        *(float4*)&Bs[bRow + 8][bC4] = b1;
        __syncthreads();

        #pragma unroll
        for (int k = 0; k < 16; k++) {
            const float4 ra0 = *(const float4*)&As[k][ty * 8];
            const float4 ra1 = *(const float4*)&As[k][ty * 8 + 4];
            const float4 rb0 = *(const float4*)&Bs[k][tx * 8];
            const float4 rb1 = *(const float4*)&Bs[k][tx * 8 + 4];
            const float a[8] = {ra0.x, ra0.y, ra0.z, ra0.w, ra1.x, ra1.y, ra1.z, ra1.w};
            const float b[8] = {rb0.x, rb0.y, rb0.z, rb0.w, rb1.x, rb1.y, rb1.z, rb1.w};
            #pragma unroll
            for (int i = 0; i < 8; i++)
                #pragma unroll
                for (int j = 0; j < 8; j++)
                    acc[i][j] = fmaf(a[i], b[j], acc[i][j]);
        }
    }

    const float4 bv0 = *(const float4*)(bias + bn + tx * 8);
    const float4 bv1 = *(const float4*)(bias + bn + tx * 8 + 4);
    const float bb[8] = {bv0.x, bv0.y, bv0.z, bv0.w, bv1.x, bv1.y, bv1.z, bv1.w};

    #pragma unroll
    for (int i = 0; i < 8; i++) {
        float* crow = C + (size_t)(bm + ty * 8 + i) * N + bn + tx * 8;
        float4 o0 = make_float4(acc[i][0] + bb[0], acc[i][1] + bb[1],
                                acc[i][2] + bb[2], acc[i][3] + bb[3]);
        float4 o1 = make_float4(acc[i][4] + bb[4], acc[i][5] + bb[5],
                                acc[i][6] + bb[6], acc[i][7] + bb[7]);
        *(float4*)(crow)     = o0;
        *(float4*)(crow + 4) = o1;
    }
}

// ---------------------------------------------------------------------------
// Flash attention, fp32, online softmax.
// Grid: (S/64, B*H). Block: 256 threads = 16(ty) x 16(tx).
// Per block: Q tile 64 rows x 64 dims; stream K/V in 32-row tiles.
// Thread owns S rows ty*4..+3 x cols tx*2..+1, and O rows ty*4..+3 x cols tx*4..+3.
// Static smem ~43 KB (< 48 KB, no attribute call needed).
// ---------------------------------------------------------------------------
__global__ __launch_bounds__(256, 2)
void flash_kernel(const float* __restrict__ q, const float* __restrict__ kv,
                  float* __restrict__ heads)
{
    __shared__ float Qt[64][68];   // Qt[d][qrow], pitch%4==0 for float4 reads
    __shared__ float Kt[64][36];   // Kt[d][krow], pitch%2==0 for float2 reads
    __shared__ float Vs[32][64];   // Vs[krow][d], natural layout
    __shared__ float Ps[64][33];   // P[qrow][krow], odd pitch for broadcast reads

    const int bh  = blockIdx.y;
    const int b   = bh >> 4;
    const int h   = bh & 15;
    const int q0  = blockIdx.x * 64;
    const int tid = threadIdx.x;
    const int tx  = tid & 15;
    const int ty  = tid >> 4;

    const float* qb = q  + (size_t)(b * Ss + q0) * Dm + h * HD;
    const float* kb = kv + (size_t)b * Ss * (2 * Dm) + h * HD;   // K heads: cols [0,D)
    const float* vb = kb + Dm;                                   // V heads: cols [D,2D)

    // Load Q tile (64x64), store transposed: Qt[d][r]
    for (int v = tid; v < 1024; v += 256) {
        const int r = v >> 4;
        const int c = (v & 15) * 4;
        const float4 t = *(const float4*)(qb + (size_t)r * Dm + c);
        Qt[c + 0][r] = t.x; Qt[c + 1][r] = t.y;
        Qt[c + 2][r] = t.z; Qt[c + 3][r] = t.w;
    }

    float m[4], l[4], o[4][4];
    #pragma unroll
    for (int i = 0; i < 4; i++) {
        m[i] = -1e30f; l[i] = 0.f;
        #pragma unroll
        for (int j = 0; j < 4; j++) o[i][j] = 0.f;
    }

    const int kr = tid >> 4;         // 0..15 (plus +16)
    const int kc = (tid & 15) * 4;   // 0..60

    for (int kt = 0; kt < Ss; kt += 32) {
        __syncthreads();   // prev iter's Kt/Vs reads and Ps reads complete

        // Load K (transposed) and V (natural) 32x64 tiles
        const float4 k0v = *(const float4*)(kb + (size_t)(kt + kr)      * (2 * Dm) + kc);
        const float4 k1v = *(const float4*)(kb + (size_t)(kt + kr + 16) * (2 * Dm) + kc);
        const float4 v0v = *(const float4*)(vb + (size_t)(kt + kr)      * (2 * Dm) + kc);
        const float4 v1v = *(const float4*)(vb + (size_t)(kt + kr + 16) * (2 * Dm) + kc);
        Kt[kc + 0][kr] = k0v.x; Kt[kc + 1][kr] = k0v.y;
        Kt[kc + 2][kr] = k0v.z; Kt[kc + 3][kr] = k0v.w;
        Kt[kc + 0][kr + 16] = k1v.x; Kt[kc + 1][kr + 16] = k1v.y;
        Kt[kc + 2][kr + 16] = k1v.z; Kt[kc + 3][kr + 16] = k1v.w;
        *(float4*)&Vs[kr][kc]      = v0v;
        *(float4*)&Vs[kr + 16][kc] = v1v;
        __syncthreads();

        // S = Q K^T (64x32 tile): thread computes 4 rows x 2 cols
        float s0[4] = {0.f, 0.f, 0.f, 0.f};
        float s1[4] = {0.f, 0.f, 0.f, 0.f};
        #pragma unroll 16
        for (int d = 0; d < 64; d++) {
            const float4 a  = *(const float4*)&Qt[d][ty * 4];
            const float2 bk = *(const float2*)&Kt[d][tx * 2];
            s0[0] = fmaf(a.x, bk.x, s0[0]); s1[0] = fmaf(a.x, bk.y, s1[0]);
            s0[1] = fmaf(a.y, bk.x, s0[1]); s1[1] = fmaf(a.y, bk.y, s1[1]);
            s0[2] = fmaf(a.z, bk.x, s0[2]); s1[2] = fmaf(a.z, bk.y, s1[2]);
            s0[3] = fmaf(a.w, bk.x, s0[3]); s1[3] = fmaf(a.w, bk.y, s1[3]);
        }

        // Scale + row max (reduce across the 16 tx lanes, width-16 butterfly)
        float rm[4];
        #pragma unroll
        for (int i = 0; i < 4; i++) {
            s0[i] *= 0.125f; s1[i] *= 0.125f;
            rm[i] = fmaxf(s0[i], s1[i]);
        }
        #pragma unroll
        for (int off = 8; off; off >>= 1) {
            #pragma unroll
            for (int i = 0; i < 4; i++)
                rm[i] = fmaxf(rm[i], __shfl_xor_sync(0xffffffffu, rm[i], off, 16));
        }

        // Online softmax update
        float rs[4];
        #pragma unroll
        for (int i = 0; i < 4; i++) {
            const float mn    = fmaxf(m[i], rm[i]);
            const float alpha = __expf(m[i] - mn);
            m[i] = mn;
            const float p0 = __expf(s0[i] - mn);
            const float p1 = __expf(s1[i] - mn);
            Ps[ty * 4 + i][tx * 2 + 0] = p0;
            Ps[ty * 4 + i][tx * 2 + 1] = p1;
            rs[i] = p0 + p1;
            l[i] *= alpha;
            o[i][0] *= alpha; o[i][1] *= alpha; o[i][2] *= alpha; o[i][3] *= alpha;
        }
        #pragma unroll
        for (int off = 8; off; off >>= 1) {
            #pragma unroll
            for (int i = 0; i < 4; i++)
                rs[i] += __shfl_xor_sync(0xffffffffu, rs[i], off, 16);
        }
        #pragma unroll
        for (int i = 0; i < 4; i++) l[i] += rs[i];

        __syncthreads();   // Ps fully written

        // O += P V : thread rows ty*4..+3, O cols tx*4..+3
        #pragma unroll 8
        for (int k2 = 0; k2 < 32; k2++) {
            const float4 vv = *(const float4*)&Vs[k2][tx * 4];
            const float p0 = Ps[ty * 4 + 0][k2];
            const float p1 = Ps[ty * 4 + 1][k2];
            const float p2 = Ps[ty * 4 + 2][k2];
            const float p3 = Ps[ty * 4 + 3][k2];
            o[0][0] = fmaf(p0, vv.x, o[0][0]); o[0][1] = fmaf(p0, vv.y, o[0][1]);
            o[0][2] = fmaf(p0, vv.z, o[0][2]); o[0][3] = fmaf(p0, vv.w, o[0][3]);
            o[1][0] = fmaf(p1, vv.x, o[1][0]); o[1][1] = fmaf(p1, vv.y, o[1][1]);
            o[1][2] = fmaf(p1, vv.z, o[1][2]); o[1][3] = fmaf(p1, vv.w, o[1][3]);
            o[2][0] = fmaf(p2, vv.x, o[2][0]); o[2][1] = fmaf(p2, vv.y, o[2][1]);
            o[2][2] = fmaf(p2, vv.z, o[2][2]); o[2][3] = fmaf(p2, vv.w, o[2][3]);
            o[3][0] = fmaf(p3, vv.x, o[3][0]); o[3][1] = fmaf(p3, vv.y, o[3][1]);
            o[3][2] = fmaf(p3, vv.z, o[3][2]); o[3][3] = fmaf(p3, vv.w, o[3][3]);
        }
    }

    // Normalize and write heads[b, q0+r, h*HD + c]
    #pragma unroll
    for (int i = 0; i < 4; i++) {
        const float inv = 1.f / l[i];
        const float4 r = make_float4(o[i][0] * inv, o[i][1] * inv,
                                     o[i][2] * inv, o[i][3] * inv);
        *(float4*)(heads + (size_t)(b * Ss + q0 + ty * 4 + i) * Dm + h * HD + tx * 4) = r;
    }
}

// ---------------------------------------------------------------------------
// Launch
// ---------------------------------------------------------------------------
extern "C" void kernel_launch(void* const* d_in, const int* in_sizes, int n_in,
                              void* d_out, int out_size)
{
    const float* query = (const float*)d_in[0];
    const float* value = (const float*)d_in[1];
    const float* Wq    = (const float*)d_in[2];
    const float* bq    = (const float*)d_in[3];
    const float* Wkv   = (const float*)d_in[4];
    const float* bkv   = (const float*)d_in[5];
    const float* Wo    = (const float*)d_in[6];
    const float* bo    = (const float*)d_in[7];
    float* out = (float*)d_out;

    float *qbuf, *kvbuf, *hbuf;
    cudaGetSymbolAddress((void**)&qbuf,  g_q);
    cudaGetSymbolAddress((void**)&kvbuf, g_kv);
    cudaGetSymbolAddress((void**)&hbuf,  g_heads);

    // 1) q = query @ Wq + bq        [8192,1024]
    gemm_bias_kernel<<<dim3(Dm / 128, M_ROWS / 128), 256>>>(
        query, Wq, bq, qbuf, M_ROWS, Dm, Dm);

    // 2) kv = value @ Wkv + bkv     [8192,2048]
    gemm_bias_kernel<<<dim3(2 * Dm / 128, M_ROWS / 128), 256>>>(
        value, Wkv, bkv, kvbuf, M_ROWS, 2 * Dm, Dm);

    // 3) heads = softmax(q k^T / sqrt(HD)) v   (per head, flash)
    flash_kernel<<<dim3(Ss / 64, Bb * Hn), 256>>>(qbuf, kvbuf, hbuf);

    // 4) out = heads @ Wo + bo      [8192,1024]
    gemm_bias_kernel<<<dim3(Dm / 128, M_ROWS / 128), 256>>>(
        hbuf, Wo, bo, out, M_ROWS, Dm, Dm);
}

// round 8
// speedup vs baseline: 1.1053x; 1.1053x over previous
#include <cuda_runtime.h>
#include <cuda_bf16.h>
#include <cstdint>

// Problem constants
#define Dm 1024
#define Hn 16
#define HD 64
#define Bb 8
#define Ss 1024
#define M_ROWS (Bb * Ss)          // 8192

// Scratch (no runtime allocation allowed)
__device__ float g_q[(size_t)M_ROWS * Dm];        // 33.5 MB
__device__ float g_kv[(size_t)M_ROWS * 2 * Dm];   // 67 MB
__device__ float g_heads[(size_t)M_ROWS * Dm];    // 33.5 MB

// ===========================================================================
// mma.sync bf16 helpers (sm_80+ PTX; lowers to HMMA on sm_103 — the only
// tensor path reachable from the harness's compute_103 virtual target)
// ===========================================================================
#define MMA16816(c, a, b)                                                     \
    asm volatile("mma.sync.aligned.m16n8k16.row.col.f32.bf16.bf16.f32 "       \
        "{%0,%1,%2,%3}, {%4,%5,%6,%7}, {%8,%9}, {%0,%1,%2,%3};"               \
        : "+f"((c)[0]), "+f"((c)[1]), "+f"((c)[2]), "+f"((c)[3])              \
        : "r"((a)[0]), "r"((a)[1]), "r"((a)[2]), "r"((a)[3]),                 \
          "r"((b)[0]), "r"((b)[1]))

// fp32 pair -> (hi bf16 pair, lo bf16 pair) packed as uint32
__device__ __forceinline__ void split2(float x, float y, uint32_t& hi, uint32_t& lo) {
    __nv_bfloat16 hx = __float2bfloat16(x), hy = __float2bfloat16(y);
    __nv_bfloat16 lx = __float2bfloat16(x - __bfloat162float(hx));
    __nv_bfloat16 ly = __float2bfloat16(y - __bfloat162float(hy));
    hi = (uint32_t)__bfloat16_as_ushort(hx) | ((uint32_t)__bfloat16_as_ushort(hy) << 16);
    lo = (uint32_t)__bfloat16_as_ushort(lx) | ((uint32_t)__bfloat16_as_ushort(ly) << 16);
}

// ===========================================================================
// HMMA GEMM + bias, bf16x3 split (fp32-accurate): C[M,N] = A[M,K]@W[K,N]+bias
// CTA tile 128x128, K-chunk 32, 8 warps (2x4), warp tile 64x32.
// Smem tiles stored K-innermost with 36-element pitch (72B = 18 words):
//   rows r..r+7 land on disjoint bank words for the m16n8k16 thread map.
// Double-buffered; loader converts fp32 -> hi/lo bf16 in flight.
// ===========================================================================
#define KC 32
#define PITCH 36                                   // bf16 elements per row
#define TILE_ELEMS (128 * PITCH)                   // one operand tile
#define TILE_BYTES (TILE_ELEMS * 2)                // 9216 B
#define BUF_BYTES  (4 * TILE_BYTES)                // Ahi,Alo,Bhi,Blo = 36864 B
#define SMEM_NEED  (2 * BUF_BYTES + 256)

__global__ __launch_bounds__(256)
void gemm_mma_kernel(const float* __restrict__ A, const float* __restrict__ W,
                     const float* __restrict__ bias, float* __restrict__ C,
                     int N, int K)
{
    extern __shared__ char smraw[];
    __nv_bfloat16* sm = (__nv_bfloat16*)smraw;

    const int tid  = threadIdx.x;
    const int lane = tid & 31;
    const int warp = tid >> 5;
    const int g    = lane >> 2;        // group id (row within 8-row block)
    const int tig  = lane & 3;         // thread in group
    const int wm   = warp >> 2;        // 0..1
    const int wn   = warp & 3;         // 0..3
    const int warp_m0 = wm * 64;
    const int warp_n0 = wn * 32;
    const int bm = blockIdx.y * 128;
    const int bn = blockIdx.x * 128;

    float acc[4][4][4];
    #pragma unroll
    for (int t = 0; t < 4; t++)
        #pragma unroll
        for (int u = 0; u < 4; u++)
            #pragma unroll
            for (int r = 0; r < 4; r++) acc[t][u][r] = 0.f;

    // ---- chunk loader: global fp32 -> split bf16 smem tiles ----
    auto load_chunk = [&](int buf, int k0) {
        __nv_bfloat16* Ah = sm + buf * (BUF_BYTES / 2);
        __nv_bfloat16* Al = Ah + TILE_ELEMS;
        __nv_bfloat16* Bh = Al + TILE_ELEMS;
        __nv_bfloat16* Bl = Bh + TILE_ELEMS;

        // A: 128 rows x 32 k fp32 = 1024 float4 / 256 thr = 4 each
        #pragma unroll
        for (int i = 0; i < 4; i++) {
            const int idx = tid + i * 256;
            const int row = idx >> 3;
            const int c4  = (idx & 7) * 4;
            const float4 a = *(const float4*)(A + (size_t)(bm + row) * K + k0 + c4);
            uint32_t h0, l0, h1, l1;
            split2(a.x, a.y, h0, l0);
            split2(a.z, a.w, h1, l1);
            *(uint2*)(Ah + row * PITCH + c4) = make_uint2(h0, h1);
            *(uint2*)(Al + row * PITCH + c4) = make_uint2(l0, l1);
        }

        // B: need Bs[n][k] = W[k0+k][bn+n]; 128 n x 16 k-pairs = 2048 items.
        // idx: n = idx&127 (coalesced across lanes), kp = idx>>7.
        #pragma unroll
        for (int i = 0; i < 8; i++) {
            const int idx = tid + i * 256;
            const int n  = idx & 127;
            const int kp = idx >> 7;
            const float* wp = W + (size_t)(k0 + 2 * kp) * N + bn + n;
            const float w0 = __ldg(wp);
            const float w1 = __ldg(wp + N);
            uint32_t hp, lp;
            split2(w0, w1, hp, lp);
            *(uint32_t*)(Bh + n * PITCH + 2 * kp) = hp;
            *(uint32_t*)(Bl + n * PITCH + 2 * kp) = lp;
        }
    };

    // ---- compute one chunk from buffer `buf` ----
    auto compute_chunk = [&](int buf) {
        const __nv_bfloat16* Ah = sm + buf * (BUF_BYTES / 2);
        const __nv_bfloat16* Al = Ah + TILE_ELEMS;
        const __nv_bfloat16* Bh = Al + TILE_ELEMS;
        const __nv_bfloat16* Bl = Bh + TILE_ELEMS;

        #pragma unroll
        for (int ks = 0; ks < KC; ks += 16) {
            uint32_t af[4][4], bh[4][2], bl[4][2];
            #pragma unroll
            for (int t = 0; t < 4; t++) {
                const __nv_bfloat16* p = Ah + (warp_m0 + t * 16 + g) * PITCH + ks + tig * 2;
                af[t][0] = *(const uint32_t*)p;
                af[t][1] = *(const uint32_t*)(p + 8 * PITCH);
                af[t][2] = *(const uint32_t*)(p + 8);
                af[t][3] = *(const uint32_t*)(p + 8 * PITCH + 8);
            }
            #pragma unroll
            for (int u = 0; u < 4; u++) {
                const __nv_bfloat16* p = Bh + (warp_n0 + u * 8 + g) * PITCH + ks + tig * 2;
                bh[u][0] = *(const uint32_t*)p;
                bh[u][1] = *(const uint32_t*)(p + 8);
                const __nv_bfloat16* q = Bl + (warp_n0 + u * 8 + g) * PITCH + ks + tig * 2;
                bl[u][0] = *(const uint32_t*)q;
                bl[u][1] = *(const uint32_t*)(q + 8);
            }
            // pass 1: hi * hi,  pass 2: hi * lo
            #pragma unroll
            for (int t = 0; t < 4; t++)
                #pragma unroll
                for (int u = 0; u < 4; u++) {
                    MMA16816(acc[t][u], af[t], bh[u]);
                    MMA16816(acc[t][u], af[t], bl[u]);
                }
            // pass 3: lo * hi (reload A regs with lo)
            #pragma unroll
            for (int t = 0; t < 4; t++) {
                const __nv_bfloat16* p = Al + (warp_m0 + t * 16 + g) * PITCH + ks + tig * 2;
                af[t][0] = *(const uint32_t*)p;
                af[t][1] = *(const uint32_t*)(p + 8 * PITCH);
                af[t][2] = *(const uint32_t*)(p + 8);
                af[t][3] = *(const uint32_t*)(p + 8 * PITCH + 8);
            }
            #pragma unroll
            for (int t = 0; t < 4; t++)
                #pragma unroll
                for (int u = 0; u < 4; u++)
                    MMA16816(acc[t][u], af[t], bh[u]);
        }
    };

    const int NC = K / KC;
    load_chunk(0, 0);
    __syncthreads();
    for (int c = 0; c < NC; c++) {
        if (c + 1 < NC) load_chunk((c + 1) & 1, (c + 1) * KC);
        compute_chunk(c & 1);
        __syncthreads();
    }

    // ---- epilogue: bias + store ----
    #pragma unroll
    for (int t = 0; t < 4; t++) {
        const int r0 = bm + warp_m0 + t * 16 + g;
        #pragma unroll
        for (int u = 0; u < 4; u++) {
            const int cb = bn + warp_n0 + u * 8 + tig * 2;
            const float2 bv = *(const float2*)(bias + cb);
            float2 o0 = make_float2(acc[t][u][0] + bv.x, acc[t][u][1] + bv.y);
            float2 o1 = make_float2(acc[t][u][2] + bv.x, acc[t][u][3] + bv.y);
            *(float2*)(C + (size_t)r0 * N + cb)       = o0;
            *(float2*)(C + (size_t)(r0 + 8) * N + cb) = o1;
        }
    }
}

// ---------------------------------------------------------------------------
// Flash attention, fp32, online softmax (unchanged from passing baseline).
// ---------------------------------------------------------------------------
__global__ __launch_bounds__(256, 2)
void flash_kernel(const float* __restrict__ q, const float* __restrict__ kv,
                  float* __restrict__ heads)
{
    __shared__ float Qt[64][68];
    __shared__ float Kt[64][36];
    __shared__ float Vs[32][64];
    __shared__ float Ps[64][33];

    const int bh  = blockIdx.y;
    const int b   = bh >> 4;
    const int h   = bh & 15;
    const int q0  = blockIdx.x * 64;
    const int tid = threadIdx.x;
    const int tx  = tid & 15;
    const int ty  = tid >> 4;

    const float* qb = q  + (size_t)(b * Ss + q0) * Dm + h * HD;
    const float* kb = kv + (size_t)b * Ss * (2 * Dm) + h * HD;
    const float* vb = kb + Dm;

    for (int v = tid; v < 1024; v += 256) {
        const int r = v >> 4;
        const int c = (v & 15) * 4;
        const float4 t = *(const float4*)(qb + (size_t)r * Dm + c);
        Qt[c + 0][r] = t.x; Qt[c + 1][r] = t.y;
        Qt[c + 2][r] = t.z; Qt[c + 3][r] = t.w;
    }

    float m[4], l[4], o[4][4];
    #pragma unroll
    for (int i = 0; i < 4; i++) {
        m[i] = -1e30f; l[i] = 0.f;
        #pragma unroll
        for (int j = 0; j < 4; j++) o[i][j] = 0.f;
    }

    const int kr = tid >> 4;
    const int kc = (tid & 15) * 4;

    for (int kt = 0; kt < Ss; kt += 32) {
        __syncthreads();

        const float4 k0v = *(const float4*)(kb + (size_t)(kt + kr)      * (2 * Dm) + kc);
        const float4 k1v = *(const float4*)(kb + (size_t)(kt + kr + 16) * (2 * Dm) + kc);
        const float4 v0v = *(const float4*)(vb + (size_t)(kt + kr)      * (2 * Dm) + kc);
        const float4 v1v = *(const float4*)(vb + (size_t)(kt + kr + 16) * (2 * Dm) + kc);
        Kt[kc + 0][kr] = k0v.x; Kt[kc + 1][kr] = k0v.y;
        Kt[kc + 2][kr] = k0v.z; Kt[kc + 3][kr] = k0v.w;
        Kt[kc + 0][kr + 16] = k1v.x; Kt[kc + 1][kr + 16] = k1v.y;
        Kt[kc + 2][kr + 16] = k1v.z; Kt[kc + 3][kr + 16] = k1v.w;
        *(float4*)&Vs[kr][kc]      = v0v;
        *(float4*)&Vs[kr + 16][kc] = v1v;
        __syncthreads();

        float s0[4] = {0.f, 0.f, 0.f, 0.f};
        float s1[4] = {0.f, 0.f, 0.f, 0.f};
        #pragma unroll 16
        for (int d = 0; d < 64; d++) {
            const float4 a  = *(const float4*)&Qt[d][ty * 4];
            const float2 bk = *(const float2*)&Kt[d][tx * 2];
            s0[0] = fmaf(a.x, bk.x, s0[0]); s1[0] = fmaf(a.x, bk.y, s1[0]);
            s0[1] = fmaf(a.y, bk.x, s0[1]); s1[1] = fmaf(a.y, bk.y, s1[1]);
            s0[2] = fmaf(a.z, bk.x, s0[2]); s1[2] = fmaf(a.z, bk.y, s1[2]);
            s0[3] = fmaf(a.w, bk.x, s0[3]); s1[3] = fmaf(a.w, bk.y, s1[3]);
        }

        float rm[4];
        #pragma unroll
        for (int i = 0; i < 4; i++) {
            s0[i] *= 0.125f; s1[i] *= 0.125f;
            rm[i] = fmaxf(s0[i], s1[i]);
        }
        #pragma unroll
        for (int off = 8; off; off >>= 1) {
            #pragma unroll
            for (int i = 0; i < 4; i++)
                rm[i] = fmaxf(rm[i], __shfl_xor_sync(0xffffffffu, rm[i], off, 16));
        }

        float rs[4];
        #pragma unroll
        for (int i = 0; i < 4; i++) {
            const float mn    = fmaxf(m[i], rm[i]);
            const float alpha = __expf(m[i] - mn);
            m[i] = mn;
            const float p0 = __expf(s0[i] - mn);
            const float p1 = __expf(s1[i] - mn);
            Ps[ty * 4 + i][tx * 2 + 0] = p0;
            Ps[ty * 4 + i][tx * 2 + 1] = p1;
            rs[i] = p0 + p1;
            l[i] *= alpha;
            o[i][0] *= alpha; o[i][1] *= alpha; o[i][2] *= alpha; o[i][3] *= alpha;
        }
        #pragma unroll
        for (int off = 8; off; off >>= 1) {
            #pragma unroll
            for (int i = 0; i < 4; i++)
                rs[i] += __shfl_xor_sync(0xffffffffu, rs[i], off, 16);
        }
        #pragma unroll
        for (int i = 0; i < 4; i++) l[i] += rs[i];

        __syncthreads();

        #pragma unroll 8
        for (int k2 = 0; k2 < 32; k2++) {
            const float4 vv = *(const float4*)&Vs[k2][tx * 4];
            const float p0 = Ps[ty * 4 + 0][k2];
            const float p1 = Ps[ty * 4 + 1][k2];
            const float p2 = Ps[ty * 4 + 2][k2];
            const float p3 = Ps[ty * 4 + 3][k2];
            o[0][0] = fmaf(p0, vv.x, o[0][0]); o[0][1] = fmaf(p0, vv.y, o[0][1]);
            o[0][2] = fmaf(p0, vv.z, o[0][2]); o[0][3] = fmaf(p0, vv.w, o[0][3]);
            o[1][0] = fmaf(p1, vv.x, o[1][0]); o[1][1] = fmaf(p1, vv.y, o[1][1]);
            o[1][2] = fmaf(p1, vv.z, o[1][2]); o[1][3] = fmaf(p1, vv.w, o[1][3]);
            o[2][0] = fmaf(p2, vv.x, o[2][0]); o[2][1] = fmaf(p2, vv.y, o[2][1]);
            o[2][2] = fmaf(p2, vv.z, o[2][2]); o[2][3] = fmaf(p2, vv.w, o[2][3]);
            o[3][0] = fmaf(p3, vv.x, o[3][0]); o[3][1] = fmaf(p3, vv.y, o[3][1]);
            o[3][2] = fmaf(p3, vv.z, o[3][2]); o[3][3] = fmaf(p3, vv.w, o[3][3]);
        }
    }

    #pragma unroll
    for (int i = 0; i < 4; i++) {
        const float inv = 1.f / l[i];
        const float4 r = make_float4(o[i][0] * inv, o[i][1] * inv,
                                     o[i][2] * inv, o[i][3] * inv);
        *(float4*)(heads + (size_t)(b * Ss + q0 + ty * 4 + i) * Dm + h * HD + tx * 4) = r;
    }
}

// ---------------------------------------------------------------------------
// Launch
// ---------------------------------------------------------------------------
extern "C" void kernel_launch(void* const* d_in, const int* in_sizes, int n_in,
                              void* d_out, int out_size)
{
    const float* query = (const float*)d_in[0];
    const float* value = (const float*)d_in[1];
    const float* Wq    = (const float*)d_in[2];
    const float* bq    = (const float*)d_in[3];
    const float* Wkv   = (const float*)d_in[4];
    const float* bkv   = (const float*)d_in[5];
    const float* Wo    = (const float*)d_in[6];
    const float* bo    = (const float*)d_in[7];
    float* out = (float*)d_out;

    float *qbuf, *kvbuf, *hbuf;
    cudaGetSymbolAddress((void**)&qbuf,  g_q);
    cudaGetSymbolAddress((void**)&kvbuf, g_kv);
    cudaGetSymbolAddress((void**)&hbuf,  g_heads);

    cudaFuncSetAttribute(gemm_mma_kernel,
                         cudaFuncAttributeMaxDynamicSharedMemorySize, SMEM_NEED);

    // 1) q = query @ Wq + bq        [8192,1024]
    gemm_mma_kernel<<<dim3(Dm / 128, M_ROWS / 128), 256, SMEM_NEED>>>(
        query, Wq, bq, qbuf, Dm, Dm);

    // 2) kv = value @ Wkv + bkv     [8192,2048]
    gemm_mma_kernel<<<dim3(2 * Dm / 128, M_ROWS / 128), 256, SMEM_NEED>>>(
        value, Wkv, bkv, kvbuf, 2 * Dm, Dm);

    // 3) heads = softmax(q k^T / sqrt(HD)) v   (per head, flash)
    flash_kernel<<<dim3(Ss / 64, Bb * Hn), 256>>>(qbuf, kvbuf, hbuf);

    // 4) out = heads @ Wo + bo      [8192,1024]
    gemm_mma_kernel<<<dim3(Dm / 128, M_ROWS / 128), 256, SMEM_NEED>>>(
        hbuf, Wo, bo, out, Dm, Dm);
}